// round 10
// baseline (speedup 1.0000x reference)
#include <cuda_runtime.h>
#include <cstdint>

// Problem constants (fixed by reference)
#define B_  32
#define T_  1024
#define D_  256
#define NM  80
#define MM  8192    // MAX_MEL = T_TEXT * MAX_DUR

#define MT  128     // tokens per CTA tile
#define KC  32      // K chunk
#define NCH (D_/KC) // 8 chunks
#define EP  36      // padded k-stride (floats) for staged tiles; conflict-free
#define CP  132     // padded t-stride for C transpose tile

// Block ranges in the fused grid
#define NB_SCAN  32
#define NB_GEMM  256
#define NB_SCAT  2048
#define GRID_TOT (NB_SCAN + NB_GEMM + NB_SCAT)

// Device scratch (no allocations allowed)
__device__ int   g_idx[B_ * MM];
__device__ int   g_len[B_];
__device__ float g_mu [B_ * NM * T_]; // [b][n][t]
__device__ int   g_done[B_];          // per-batch completion counters (scan+8 gemm)

// dynamic smem layout (float units)
#define SF_EHI 0                        // 128 x EP
#define SF_WHI (SF_EHI + MT * EP)       // 80 x EP
#define SF_WLO (SF_WHI + NM * EP)       // 80 x EP
#define SF_TOT (SF_WLO + NM * EP)       // 10368 floats = 41472 B
#define SM_TOTAL (NM * CP * 4)          // 42240 B (epilogue transpose tile dominates)

__device__ __forceinline__ float to_tf32(float a) {
    uint32_t r;
    asm("cvt.rna.tf32.f32 %0, %1;" : "=r"(r) : "f"(a));
    return __uint_as_float(r);
}
__device__ __forceinline__ void mma_tf32(float c[4], const uint32_t a[4],
                                         const uint32_t b[2]) {
    asm volatile(
        "mma.sync.aligned.m16n8k8.row.col.f32.tf32.tf32.f32 "
        "{%0,%1,%2,%3}, {%4,%5,%6,%7}, {%8,%9}, {%0,%1,%2,%3};"
        : "+f"(c[0]), "+f"(c[1]), "+f"(c[2]), "+f"(c[3])
        : "r"(a[0]), "r"(a[1]), "r"(a[2]), "r"(a[3]), "r"(b[0]), "r"(b[1]));
}
__device__ __forceinline__ int ld_acquire(const int* p) {
    int v;
    asm volatile("ld.acquire.gpu.global.s32 %0, [%1];" : "=r"(v) : "l"(p) : "memory");
    return v;
}

__global__ void zero_flags() {
    if (threadIdx.x < B_) g_done[threadIdx.x] = 0;
}

// ---------------------------------------------------------------------------
// Fused kernel: scan [0,32) | gemm [32,288) | scatter [288,2336)
// GEMM: 2-product TF32 split  D = Ehi*Whi + Ehi*Wlo  (rna hi; |err|~3e-4)
// ---------------------------------------------------------------------------
__global__ __launch_bounds__(256)
void fused_kernel(const float* __restrict__ E, const float* __restrict__ W,
                  const float* __restrict__ bmu, const int* __restrict__ dur,
                  float* __restrict__ out, int write_mask) {
    extern __shared__ float sm[];
    const int tid = threadIdx.x;
    const int bx  = blockIdx.x;

    if (bx < NB_SCAN) {
        // ================= scan branch =================
        const int b = bx;
        int* wsum = reinterpret_cast<int*>(sm);
        int* sLp  = reinterpret_cast<int*>(sm) + 16;
        const int lane = tid & 31;
        const int wid  = tid >> 5;
        int4 d4 = *reinterpret_cast<const int4*>(dur + b * T_ + tid * 4);
        int s = d4.x + d4.y + d4.z + d4.w;
#pragma unroll
        for (int off = 1; off < 32; off <<= 1) {
            int v = __shfl_up_sync(0xffffffffu, s, off);
            if (lane >= off) s += v;
        }
        if (lane == 31) wsum[wid] = s;
        __syncthreads();
        int base = 0;
#pragma unroll
        for (int w = 0; w < 8; ++w) base += (w < wid) ? wsum[w] : 0;
        const int end3  = base + s;
        const int start = end3 - (d4.x + d4.y + d4.z + d4.w);
        const int c0 = start + d4.x;
        const int c1 = c0 + d4.y;
        const int c2 = c1 + d4.z;
        int* ib = g_idx + b * MM;
        const int t0 = tid * 4;
        for (int p = start; p < c0;   ++p) ib[p] = t0 + 0;
        for (int p = c0;    p < c1;   ++p) ib[p] = t0 + 1;
        for (int p = c1;    p < c2;   ++p) ib[p] = t0 + 2;
        for (int p = c2;    p < end3; ++p) ib[p] = t0 + 3;
        if (tid == 255) { g_len[b] = end3; *sLp = end3; }
        __syncthreads();
        if (write_mask) {
            const int L = *sLp;
            float* maskb = out + (size_t)B_ * NM * MM + (size_t)b * MM;
#pragma unroll
            for (int i = 0; i < 8; ++i) {
                const int g = (tid + i * 256) * 4;
                float4 m;
                m.x = (g + 0 < L) ? 1.0f : 0.0f;
                m.y = (g + 1 < L) ? 1.0f : 0.0f;
                m.z = (g + 2 < L) ? 1.0f : 0.0f;
                m.w = (g + 3 < L) ? 1.0f : 0.0f;
                *reinterpret_cast<float4*>(maskb + g) = m;
            }
        }
        __threadfence();
        __syncthreads();
        if (tid == 0) atomicAdd(&g_done[b], 1);
        return;
    }

    if (bx < NB_SCAN + NB_GEMM) {
        // ================= GEMM branch =================
        const int gb   = bx - NB_SCAN;
        const int b    = gb >> 3;
        const int t0   = (gb & 7) * MT;
        const int wid  = tid >> 5;
        const int lane = tid & 31;
        const int m_base = (wid >> 1) * 32;
        const int n_base = (wid & 1) * 40;
        const int gr = lane >> 2;
        const int tg = lane & 3;

        float* sEhi = sm + SF_EHI;
        float* sWhi = sm + SF_WHI;
        float* sWlo = sm + SF_WLO;
        const uint32_t* uEhi = reinterpret_cast<const uint32_t*>(sEhi);
        const uint32_t* uWhi = reinterpret_cast<const uint32_t*>(sWhi);
        const uint32_t* uWlo = reinterpret_cast<const uint32_t*>(sWlo);

        float acc[2][5][4];
#pragma unroll
        for (int mt = 0; mt < 2; ++mt)
#pragma unroll
            for (int nt = 0; nt < 5; ++nt)
#pragma unroll
                for (int j = 0; j < 4; ++j) acc[mt][nt][j] = 0.0f;

        // register prefetch buffers
        float4 eR[4];
        float4 wR[3];
        const float* Eb = E + ((size_t)b * T_ + t0) * D_;

        // prefetch chunk 0
#pragma unroll
        for (int i = 0; i < 4; ++i) {
            const int q = tid + i * 256;
            eR[i] = *reinterpret_cast<const float4*>(Eb + (size_t)(q >> 3) * D_ + (q & 7) * 4);
        }
#pragma unroll
        for (int i = 0; i < 3; ++i) {
            const int q = tid + i * 256;
            if (q < NM * 8)
                wR[i] = *reinterpret_cast<const float4*>(W + (q >> 3) * D_ + (q & 7) * 4);
        }

        for (int ch = 0; ch < NCH; ++ch) {
            __syncthreads();   // smem free (MMA of previous chunk done)
#pragma unroll
            for (int i = 0; i < 4; ++i) {
                const int q = tid + i * 256;
                const int r = q >> 3, kf = q & 7;
                float4 v = eR[i];
                float4 hi;
                hi.x = to_tf32(v.x); hi.y = to_tf32(v.y);
                hi.z = to_tf32(v.z); hi.w = to_tf32(v.w);
                *reinterpret_cast<float4*>(sEhi + r * EP + kf * 4) = hi;
            }
#pragma unroll
            for (int i = 0; i < 3; ++i) {
                const int q = tid + i * 256;
                if (q < NM * 8) {
                    const int n = q >> 3, kf = q & 7;
                    float4 v = wR[i];
                    float4 hi, lo;
                    hi.x = to_tf32(v.x); lo.x = to_tf32(v.x - hi.x);
                    hi.y = to_tf32(v.y); lo.y = to_tf32(v.y - hi.y);
                    hi.z = to_tf32(v.z); lo.z = to_tf32(v.z - hi.z);
                    hi.w = to_tf32(v.w); lo.w = to_tf32(v.w - hi.w);
                    *reinterpret_cast<float4*>(sWhi + n * EP + kf * 4) = hi;
                    *reinterpret_cast<float4*>(sWlo + n * EP + kf * 4) = lo;
                }
            }
            __syncthreads();
            // issue prefetch of next chunk (latency hidden behind MMAs)
            if (ch + 1 < NCH) {
                const int kc = (ch + 1) * KC;
#pragma unroll
                for (int i = 0; i < 4; ++i) {
                    const int q = tid + i * 256;
                    eR[i] = *reinterpret_cast<const float4*>(
                        Eb + (size_t)(q >> 3) * D_ + kc + (q & 7) * 4);
                }
#pragma unroll
                for (int i = 0; i < 3; ++i) {
                    const int q = tid + i * 256;
                    if (q < NM * 8)
                        wR[i] = *reinterpret_cast<const float4*>(
                            W + (q >> 3) * D_ + kc + (q & 7) * 4);
                }
            }

#pragma unroll
            for (int ks = 0; ks < KC / 8; ++ks) {
                const int k0 = ks * 8;
                uint32_t bhi[5][2], blo[5][2];
#pragma unroll
                for (int nt = 0; nt < 5; ++nt) {
                    const int rB = (n_base + nt * 8 + gr) * EP + k0 + tg;
                    bhi[nt][0] = uWhi[rB];
                    bhi[nt][1] = uWhi[rB + 4];
                    blo[nt][0] = uWlo[rB];
                    blo[nt][1] = uWlo[rB + 4];
                }
#pragma unroll
                for (int mt = 0; mt < 2; ++mt) {
                    const int rA = (m_base + mt * 16 + gr) * EP + k0 + tg;
                    uint32_t ahi[4];
                    ahi[0] = uEhi[rA];
                    ahi[1] = uEhi[rA + 8 * EP];
                    ahi[2] = uEhi[rA + 4];
                    ahi[3] = uEhi[rA + 8 * EP + 4];
#pragma unroll
                    for (int nt = 0; nt < 5; ++nt) {
                        mma_tf32(acc[mt][nt], ahi, bhi[nt]);
                        mma_tf32(acc[mt][nt], ahi, blo[nt]);
                    }
                }
            }
        }
        __syncthreads();

        // Epilogue: C frags -> smem [n][t] transpose -> coalesced stores + bias
        float* sC = sm;
#pragma unroll
        for (int mt = 0; mt < 2; ++mt) {
            const int row = m_base + mt * 16 + gr;
#pragma unroll
            for (int nt = 0; nt < 5; ++nt) {
                const int col = n_base + nt * 8 + 2 * tg;
                sC[(col + 0) * CP + row]     = acc[mt][nt][0];
                sC[(col + 1) * CP + row]     = acc[mt][nt][1];
                sC[(col + 0) * CP + row + 8] = acc[mt][nt][2];
                sC[(col + 1) * CP + row + 8] = acc[mt][nt][3];
            }
        }
        __syncthreads();

        for (int q = tid; q < NM * (MT / 4); q += 256) {
            const int n = q >> 5;
            const int f = q & 31;
            const float bv = __ldg(bmu + n);
            float4 v = *reinterpret_cast<const float4*>(sC + n * CP + f * 4);
            v.x += bv; v.y += bv; v.z += bv; v.w += bv;
            *reinterpret_cast<float4*>(g_mu + ((size_t)b * NM + n) * T_ + t0 + f * 4) = v;
        }
        __threadfence();
        __syncthreads();
        if (tid == 0) atomicAdd(&g_done[b], 1);
        return;
    }

    // ================= scatter branch =================
    {
        const int id = bx - (NB_SCAN + NB_GEMM);
        const int b  = id >> 6;
        const int f0 = (id & 63) * 128;

        if (tid == 0) {
            while (ld_acquire(&g_done[b]) < 9) __nanosleep(256);
        }
        __syncthreads();
        __threadfence();

        __shared__ int sidx[128];
        const int L = g_len[b];
        if (tid < 128) {
            const int p = f0 + tid;
            const int t = g_idx[b * MM + p];
            sidx[tid] = (p < L) ? t : -1;
        }
        __syncthreads();

        const int n0 = tid >> 5;
        const int g  = (tid & 31) * 4;
        const int t0 = sidx[g + 0];
        const int t1 = sidx[g + 1];
        const int t2 = sidx[g + 2];
        const int t3 = sidx[g + 3];

        const float* mb = g_mu + (size_t)b * NM * T_;
        float* ob = out + (size_t)b * NM * MM + f0 + g;

#pragma unroll
        for (int j = 0; j < 10; ++j) {
            const int n = n0 + 8 * j;
            const float* r = mb + (size_t)n * T_;
            float4 o;
            o.x = (t0 >= 0) ? __ldg(r + t0) : 0.0f;
            o.y = (t1 >= 0) ? __ldg(r + t1) : 0.0f;
            o.z = (t2 >= 0) ? __ldg(r + t2) : 0.0f;
            o.w = (t3 >= 0) ? __ldg(r + t3) : 0.0f;
            *reinterpret_cast<float4*>(ob + (size_t)n * MM) = o;
        }
    }
}

// ---------------------------------------------------------------------------
extern "C" void kernel_launch(void* const* d_in, const int* in_sizes, int n_in,
                              void* d_out, int out_size) {
    const float* E   = nullptr;
    const int*   dur = nullptr;
    const float* W   = nullptr;
    const float* bmu = nullptr;
    for (int i = 0; i < n_in; ++i) {
        switch (in_sizes[i]) {
            case B_ * T_ * D_: E   = (const float*)d_in[i]; break;
            case B_ * T_:      dur = (const int*)  d_in[i]; break;
            case NM * D_:      W   = (const float*)d_in[i]; break;
            case NM:           bmu = (const float*)d_in[i]; break;
            default: break;
        }
    }
    float* out = (float*)d_out;
    const int mu_elems = B_ * NM * MM;
    const int write_mask = (out_size >= mu_elems + B_ * MM) ? 1 : 0;

    cudaFuncSetAttribute(fused_kernel,
                         cudaFuncAttributeMaxDynamicSharedMemorySize, SM_TOTAL);

    zero_flags<<<1, 32>>>();
    fused_kernel<<<GRID_TOT, 256, SM_TOTAL>>>(E, W, bmu, dur, out, write_mask);
}

// round 11
// speedup vs baseline: 1.1456x; 1.1456x over previous
#include <cuda_runtime.h>
#include <cstdint>

// Problem constants (fixed by reference)
#define B_  32
#define T_  1024
#define D_  256
#define NM  80
#define MM  8192    // MAX_MEL = T_TEXT * MAX_DUR

#define MT  64      // tokens per CTA tile (M-split)
#define KC  32      // K chunk
#define NCH (D_/KC) // 8 chunks
#define KP  20      // stride of staged tiles in u32 (bf16x2) units; conflict-free
#define CP  68      // padded t-stride for C transpose tile (64+4)

// Block ranges in the fused grid
#define NB_SCAN  32
#define NB_GEMM  512
#define NB_SCAT  2048
#define GRID_TOT (NB_SCAN + NB_GEMM + NB_SCAT)
#define DONE_TGT 17     // 16 gemm tiles + 1 scan per batch

// Device scratch (no allocations allowed)
__device__ int   g_idx[B_ * MM];
__device__ int   g_len[B_];
__device__ float g_mu [B_ * NM * T_]; // [b][n][t]
__device__ int   g_done[B_];

// dynamic smem layout (u32 units)
#define SU_EHI 0                        // 64 x KP
#define SU_ELO (SU_EHI + MT * KP)
#define SU_WHI (SU_ELO + MT * KP)       // 80 x KP
#define SU_WLO (SU_WHI + NM * KP)
#define SU_TOT (SU_WLO + NM * KP)       // 5760 u32 = 23040 B
// epilogue tile: 80*CP floats = 21760 B (fits under SU_TOT)
#define SM_TOTAL (SU_TOT * 4)

// pack two floats' bf16-truncations
__device__ __forceinline__ uint32_t hi_pair(float ax, float ay) {
    return __byte_perm(__float_as_uint(ax), __float_as_uint(ay), 0x7632);
}
__device__ __forceinline__ float hi_of(float a) {
    return __uint_as_float(__float_as_uint(a) & 0xFFFF0000u);
}
__device__ __forceinline__ uint32_t lo_pair(float lx, float ly) {
    uint32_t r;
    asm("cvt.rn.bf16x2.f32 %0, %1, %2;" : "=r"(r) : "f"(ly), "f"(lx));
    return r;
}
__device__ __forceinline__ void mma_bf16(float c[4], const uint32_t a[4],
                                         const uint32_t b[2]) {
    asm volatile(
        "mma.sync.aligned.m16n8k16.row.col.f32.bf16.bf16.f32 "
        "{%0,%1,%2,%3}, {%4,%5,%6,%7}, {%8,%9}, {%0,%1,%2,%3};"
        : "+f"(c[0]), "+f"(c[1]), "+f"(c[2]), "+f"(c[3])
        : "r"(a[0]), "r"(a[1]), "r"(a[2]), "r"(a[3]), "r"(b[0]), "r"(b[1]));
}
__device__ __forceinline__ int ld_acquire(const int* p) {
    int v;
    asm volatile("ld.acquire.gpu.global.s32 %0, [%1];" : "=r"(v) : "l"(p) : "memory");
    return v;
}

__global__ void zero_flags() {
    if (threadIdx.x < B_) g_done[threadIdx.x] = 0;
}

// ---------------------------------------------------------------------------
// Fused kernel: scan [0,32) | gemm [32,544) | scatter [544,2592)
// GEMM: bf16 3-product split (Ehi*Whi + Ehi*Wlo + Elo*Whi), 64x80 tiles.
// ---------------------------------------------------------------------------
__global__ __launch_bounds__(256)
void fused_kernel(const float* __restrict__ E, const float* __restrict__ W,
                  const float* __restrict__ bmu, const int* __restrict__ dur,
                  float* __restrict__ out, int write_mask) {
    extern __shared__ float sm[];
    uint32_t* su = reinterpret_cast<uint32_t*>(sm);
    const int tid = threadIdx.x;
    const int bx  = blockIdx.x;

    if (bx < NB_SCAN) {
        // ================= scan branch =================
        const int b = bx;
        int* wsum = reinterpret_cast<int*>(sm);
        int* sLp  = reinterpret_cast<int*>(sm) + 16;
        const int lane = tid & 31;
        const int wid  = tid >> 5;
        int4 d4 = *reinterpret_cast<const int4*>(dur + b * T_ + tid * 4);
        int s = d4.x + d4.y + d4.z + d4.w;
#pragma unroll
        for (int off = 1; off < 32; off <<= 1) {
            int v = __shfl_up_sync(0xffffffffu, s, off);
            if (lane >= off) s += v;
        }
        if (lane == 31) wsum[wid] = s;
        __syncthreads();
        int base = 0;
#pragma unroll
        for (int w = 0; w < 8; ++w) base += (w < wid) ? wsum[w] : 0;
        const int end3  = base + s;
        const int start = end3 - (d4.x + d4.y + d4.z + d4.w);
        const int c0 = start + d4.x;
        const int c1 = c0 + d4.y;
        const int c2 = c1 + d4.z;
        int* ib = g_idx + b * MM;
        const int t0 = tid * 4;
        for (int p = start; p < c0;   ++p) ib[p] = t0 + 0;
        for (int p = c0;    p < c1;   ++p) ib[p] = t0 + 1;
        for (int p = c1;    p < c2;   ++p) ib[p] = t0 + 2;
        for (int p = c2;    p < end3; ++p) ib[p] = t0 + 3;
        if (tid == 255) { g_len[b] = end3; *sLp = end3; }
        __syncthreads();
        if (write_mask) {
            const int L = *sLp;
            float* maskb = out + (size_t)B_ * NM * MM + (size_t)b * MM;
#pragma unroll
            for (int i = 0; i < 8; ++i) {
                const int g = (tid + i * 256) * 4;
                float4 m;
                m.x = (g + 0 < L) ? 1.0f : 0.0f;
                m.y = (g + 1 < L) ? 1.0f : 0.0f;
                m.z = (g + 2 < L) ? 1.0f : 0.0f;
                m.w = (g + 3 < L) ? 1.0f : 0.0f;
                *reinterpret_cast<float4*>(maskb + g) = m;
            }
        }
        __threadfence();
        __syncthreads();
        if (tid == 0) atomicAdd(&g_done[b], 1);
        return;
    }

    if (bx < NB_SCAN + NB_GEMM) {
        // ================= GEMM branch =================
        const int gb   = bx - NB_SCAN;
        const int b    = gb >> 4;
        const int t0   = (gb & 15) * MT;
        const int wid  = tid >> 5;
        const int lane = tid & 31;
        const int m_base = (wid >> 1) * 16;   // 4 m-groups of 16 rows
        const int n_base = (wid & 1) * 40;    // 2 n-groups of 40 cols
        const int gr = lane >> 2;
        const int tg = lane & 3;

        uint32_t* uEhi = su + SU_EHI;
        uint32_t* uElo = su + SU_ELO;
        uint32_t* uWhi = su + SU_WHI;
        uint32_t* uWlo = su + SU_WLO;

        float acc[5][4];
#pragma unroll
        for (int nt = 0; nt < 5; ++nt)
#pragma unroll
            for (int j = 0; j < 4; ++j) acc[nt][j] = 0.0f;

        // register prefetch buffers
        float4 eR[2];
        float4 wR[3];
        const float* Eb = E + ((size_t)b * T_ + t0) * D_;

        // prefetch chunk 0 (E: 64x8 float4 = 512; W: 80x8 = 640)
#pragma unroll
        for (int i = 0; i < 2; ++i) {
            const int q = tid + i * 256;
            eR[i] = *reinterpret_cast<const float4*>(Eb + (size_t)(q >> 3) * D_ + (q & 7) * 4);
        }
#pragma unroll
        for (int i = 0; i < 3; ++i) {
            const int q = tid + i * 256;
            if (q < NM * 8)
                wR[i] = *reinterpret_cast<const float4*>(W + (q >> 3) * D_ + (q & 7) * 4);
        }

        for (int ch = 0; ch < NCH; ++ch) {
            __syncthreads();   // smem free (MMA of previous chunk done)
#pragma unroll
            for (int i = 0; i < 2; ++i) {
                const int q = tid + i * 256;
                const int r = q >> 3, kf = q & 7;
                float4 v = eR[i];
                uint2 hp, lp;
                hp.x = hi_pair(v.x, v.y);
                hp.y = hi_pair(v.z, v.w);
                lp.x = lo_pair(v.x - hi_of(v.x), v.y - hi_of(v.y));
                lp.y = lo_pair(v.z - hi_of(v.z), v.w - hi_of(v.w));
                *reinterpret_cast<uint2*>(uEhi + r * KP + kf * 2) = hp;
                *reinterpret_cast<uint2*>(uElo + r * KP + kf * 2) = lp;
            }
#pragma unroll
            for (int i = 0; i < 3; ++i) {
                const int q = tid + i * 256;
                if (q < NM * 8) {
                    const int n = q >> 3, kf = q & 7;
                    float4 v = wR[i];
                    uint2 hp, lp;
                    hp.x = hi_pair(v.x, v.y);
                    hp.y = hi_pair(v.z, v.w);
                    lp.x = lo_pair(v.x - hi_of(v.x), v.y - hi_of(v.y));
                    lp.y = lo_pair(v.z - hi_of(v.z), v.w - hi_of(v.w));
                    *reinterpret_cast<uint2*>(uWhi + n * KP + kf * 2) = hp;
                    *reinterpret_cast<uint2*>(uWlo + n * KP + kf * 2) = lp;
                }
            }
            __syncthreads();
            // issue prefetch of next chunk (latency hidden behind MMAs)
            if (ch + 1 < NCH) {
                const int kc = (ch + 1) * KC;
#pragma unroll
                for (int i = 0; i < 2; ++i) {
                    const int q = tid + i * 256;
                    eR[i] = *reinterpret_cast<const float4*>(
                        Eb + (size_t)(q >> 3) * D_ + kc + (q & 7) * 4);
                }
#pragma unroll
                for (int i = 0; i < 3; ++i) {
                    const int q = tid + i * 256;
                    if (q < NM * 8)
                        wR[i] = *reinterpret_cast<const float4*>(
                            W + (q >> 3) * D_ + kc + (q & 7) * 4);
                }
            }

#pragma unroll
            for (int ks = 0; ks < KC / 16; ++ks) {
                const int kp0 = ks * 8;
                uint32_t bhi[5][2], blo[5][2];
#pragma unroll
                for (int nt = 0; nt < 5; ++nt) {
                    const int rB = (n_base + nt * 8 + gr) * KP + kp0 + tg;
                    bhi[nt][0] = uWhi[rB];
                    bhi[nt][1] = uWhi[rB + 4];
                    blo[nt][0] = uWlo[rB];
                    blo[nt][1] = uWlo[rB + 4];
                }
                const int rA = (m_base + gr) * KP + kp0 + tg;
                uint32_t ahi[4], alo[4];
                ahi[0] = uEhi[rA];
                ahi[1] = uEhi[rA + 8 * KP];
                ahi[2] = uEhi[rA + 4];
                ahi[3] = uEhi[rA + 8 * KP + 4];
                alo[0] = uElo[rA];
                alo[1] = uElo[rA + 8 * KP];
                alo[2] = uElo[rA + 4];
                alo[3] = uElo[rA + 8 * KP + 4];
#pragma unroll
                for (int nt = 0; nt < 5; ++nt) {
                    mma_bf16(acc[nt], ahi, bhi[nt]);
                    mma_bf16(acc[nt], ahi, blo[nt]);
                    mma_bf16(acc[nt], alo, bhi[nt]);
                }
            }
        }
        __syncthreads();

        // Epilogue: C frags -> smem [n][t] transpose -> coalesced stores + bias
        float* sC = sm;   // 80 x CP floats
        {
            const int row = m_base + gr;
#pragma unroll
            for (int nt = 0; nt < 5; ++nt) {
                const int col = n_base + nt * 8 + 2 * tg;
                sC[(col + 0) * CP + row]     = acc[nt][0];
                sC[(col + 1) * CP + row]     = acc[nt][1];
                sC[(col + 0) * CP + row + 8] = acc[nt][2];
                sC[(col + 1) * CP + row + 8] = acc[nt][3];
            }
        }
        __syncthreads();

        for (int q = tid; q < NM * (MT / 4); q += 256) {
            const int n = q >> 4;           // MT/4 = 16 float4 per row
            const int f = q & 15;
            const float bv = __ldg(bmu + n);
            float4 v = *reinterpret_cast<const float4*>(sC + n * CP + f * 4);
            v.x += bv; v.y += bv; v.z += bv; v.w += bv;
            *reinterpret_cast<float4*>(g_mu + ((size_t)b * NM + n) * T_ + t0 + f * 4) = v;
        }
        __threadfence();
        __syncthreads();
        if (tid == 0) atomicAdd(&g_done[b], 1);
        return;
    }

    // ================= scatter branch =================
    {
        const int id = bx - (NB_SCAN + NB_GEMM);
        const int b  = id >> 6;
        const int f0 = (id & 63) * 128;

        if (tid == 0) {
            while (ld_acquire(&g_done[b]) < DONE_TGT) __nanosleep(128);
        }
        __syncthreads();
        __threadfence();

        __shared__ int sidx[128];
        const int L = g_len[b];
        if (tid < 128) {
            const int p = f0 + tid;
            const int t = g_idx[b * MM + p];
            sidx[tid] = (p < L) ? t : -1;
        }
        __syncthreads();

        const int n0 = tid >> 5;
        const int g  = (tid & 31) * 4;
        const int t0 = sidx[g + 0];
        const int t1 = sidx[g + 1];
        const int t2 = sidx[g + 2];
        const int t3 = sidx[g + 3];

        const float* mb = g_mu + (size_t)b * NM * T_;
        float* ob = out + (size_t)b * NM * MM + f0 + g;

#pragma unroll
        for (int j = 0; j < 10; ++j) {
            const int n = n0 + 8 * j;
            const float* r = mb + (size_t)n * T_;
            float4 o;
            o.x = (t0 >= 0) ? __ldg(r + t0) : 0.0f;
            o.y = (t1 >= 0) ? __ldg(r + t1) : 0.0f;
            o.z = (t2 >= 0) ? __ldg(r + t2) : 0.0f;
            o.w = (t3 >= 0) ? __ldg(r + t3) : 0.0f;
            *reinterpret_cast<float4*>(ob + (size_t)n * MM) = o;
        }
    }
}

// ---------------------------------------------------------------------------
extern "C" void kernel_launch(void* const* d_in, const int* in_sizes, int n_in,
                              void* d_out, int out_size) {
    const float* E   = nullptr;
    const int*   dur = nullptr;
    const float* W   = nullptr;
    const float* bmu = nullptr;
    for (int i = 0; i < n_in; ++i) {
        switch (in_sizes[i]) {
            case B_ * T_ * D_: E   = (const float*)d_in[i]; break;
            case B_ * T_:      dur = (const int*)  d_in[i]; break;
            case NM * D_:      W   = (const float*)d_in[i]; break;
            case NM:           bmu = (const float*)d_in[i]; break;
            default: break;
        }
    }
    float* out = (float*)d_out;
    const int mu_elems = B_ * NM * MM;
    const int write_mask = (out_size >= mu_elems + B_ * MM) ? 1 : 0;

    cudaFuncSetAttribute(fused_kernel,
                         cudaFuncAttributeMaxDynamicSharedMemorySize, SM_TOTAL);

    zero_flags<<<1, 32>>>();
    fused_kernel<<<GRID_TOT, 256, SM_TOTAL>>>(E, W, bmu, dur, out, write_mask);
}